// round 4
// baseline (speedup 1.0000x reference)
#include <cuda_runtime.h>
#include <cuda_bf16.h>

// y[i,h,b] = sum_{kj,kh,l} w[i,kj,kh,l] * U[h+kj-1, kh, b, l]   (zero pad on h+kj-1)
// U[ap,kh,b,l] = T(ap,kh,(b-1)%14, l+128) + T(ap,kh,b,l)
// T(ap,kh,b',c) = (0 <= b'+kh-1 < 14) ? x[c, ap, (b'+kh-2) mod 14] : 0

#define U_ELEMS (14 * 3 * 14 * 128)   // 75264

__device__ float g_U[U_ELEMS];

__global__ void build_u_kernel(const float* __restrict__ x) {
    int e = blockIdx.x * blockDim.x + threadIdx.x;   // 294*256 == 75264 exactly
    int l  = e & 127;
    int b  = (e >> 7) % 14;
    int kh = (e / (128 * 14)) % 3;
    int ap = e / (128 * 14 * 3);

    float val = 0.0f;
    int t = b + kh - 1;
    if (t >= 0 && t < 14) {
        int wsrc = t - 1; if (wsrc < 0) wsrc += 14;
        val += x[l * 196 + ap * 14 + wsrc];
    }
    int bm = b - 1; if (bm < 0) bm += 14;
    int t1 = bm + kh - 1;
    if (t1 >= 0 && t1 < 14) {
        int wsrc = t1 - 1; if (wsrc < 0) wsrc += 14;
        val += x[(l + 128) * 196 + ap * 14 + wsrc];
    }
    g_U[e] = val;
}

// Grid: (a=14, i-tile=8, kj=3). Block: 256 threads, 8 warps.
// Each block: 32 output channels (lane = i), 14 b's, K-slice = 384 (one kj),
// split-K across 8 warps (48 k each). w loaded direct from L2 (no reuse in block).
__global__ __launch_bounds__(256)
void gemm_kernel(const float* __restrict__ w, float* __restrict__ y) {
    __shared__ float u_s[5376];           // [kh=3][b=14][l=128] for this block's ap
    __shared__ float red[8 * 14 * 32];    // [warp][b][lane]

    const int a   = blockIdx.x;           // 0..13
    const int i0  = blockIdx.y * 32;
    const int kj  = blockIdx.z;           // 0..2
    const int tid = threadIdx.x;

    const int ap = a - 1 + kj;
    if (ap < 0 || ap >= 14) return;       // whole block contributes zero

    // ---- stage U[ap] slice: 5376 floats, coalesced float4 ----
    const float4* U4 = (const float4*)(g_U + ap * 5376);
    float4* u4s = (float4*)u_s;
    for (int idx = tid; idx < 5376 / 4; idx += 256) u4s[idx] = U4[idx];
    __syncthreads();

    const int warp = tid >> 5;
    const int lane = tid & 31;

    float acc[14];
#pragma unroll
    for (int b = 0; b < 14; b++) acc[b] = 0.f;

    // w row (i0+lane), k range [kj*384 + warp*48, +48): 12 float4 loads from L2
    const float4* wp = (const float4*)w + (i0 + lane) * 288 + kj * 96 + warp * 12;
    const float4* u4 = (const float4*)u_s;

#pragma unroll 4
    for (int t = 0; t < 12; t++) {
        float4 wv = wp[t];                        // direct LDG (L2-hit), no reuse
        int k  = warp * 48 + t * 4;               // local k within kj slice
        int ub = (((k >> 7) * 1792) + (k & 127)) >> 2;  // float4 idx, b=0
#pragma unroll
        for (int b = 0; b < 14; b++) {
            float4 uv = u4[ub + b * 32];          // warp-broadcast LDS
            acc[b] = fmaf(wv.x, uv.x, acc[b]);
            acc[b] = fmaf(wv.y, uv.y, acc[b]);
            acc[b] = fmaf(wv.z, uv.z, acc[b]);
            acc[b] = fmaf(wv.w, uv.w, acc[b]);
        }
    }

    // ---- cross-warp reduction then atomic combine across kj blocks ----
#pragma unroll
    for (int b = 0; b < 14; b++) red[(warp * 14 + b) * 32 + lane] = acc[b];
    __syncthreads();

    for (int o = tid; o < 14 * 32; o += 256) {
        int b = o >> 5;
        int i = o & 31;
        float s = 0.f;
#pragma unroll
        for (int wq = 0; wq < 8; wq++) s += red[(wq * 14 + b) * 32 + i];
        atomicAdd(&y[(i0 + i) * 196 + a * 14 + b], s);
    }
}

extern "C" void kernel_launch(void* const* d_in, const int* in_sizes, int n_in,
                              void* d_out, int out_size) {
    const float* x = (const float*)d_in[0];
    const float* w = (const float*)d_in[1];
    float* y = (float*)d_out;

    cudaMemsetAsync(y, 0, (size_t)out_size * sizeof(float));
    build_u_kernel<<<294, 256>>>(x);
    gemm_kernel<<<dim3(14, 8, 3), 256>>>(w, y);
}

// round 5
// speedup vs baseline: 1.2164x; 1.2164x over previous
#include <cuda_runtime.h>
#include <cuda_bf16.h>

// y[i,a,b] = sum_{kj,kh,l} w[i,kj,kh,l] * U[a+kj-1, kh, b, l]   (zero pad on a+kj-1)
// U[ap,kh,b,l] = T(ap,kh,(b-1)%14, l+128) + T(ap,kh,b,l)
// T(ap,kh,b',c) = (0 <= b'+kh-1 < 14) ? x[c, ap, (b'+kh-2) mod 14] : 0

#define U_ELEMS (14 * 3 * 14 * 128)     // 75264
#define W_ELEMS (256 * 1152)            // 294912
#define U_BLOCKS 294                     // 294*256 == 75264
#define W_BLOCKS 1152                    // 1152*256 == 294912
#define GEMM_SMEM (16128 * 4)            // 64512 B: [9][14][128] floats

__device__ float g_U[U_ELEMS];
__device__ float g_Wt[W_ELEMS];          // packed: [k/4][i=256][4]  (i-coalesced)

// Fused prep: blocks [0,294) build U; blocks [294,1446) transpose/pack w.
__global__ void prep_kernel(const float* __restrict__ x, const float* __restrict__ w) {
    if (blockIdx.x < U_BLOCKS) {
        int e = blockIdx.x * 256 + threadIdx.x;      // < 75264
        int l  = e & 127;
        int b  = (e >> 7) % 14;
        int kh = (e / (128 * 14)) % 3;
        int ap = e / (128 * 14 * 3);

        float val = 0.0f;
        int t = b + kh - 1;
        if (t >= 0 && t < 14) {
            int wsrc = t - 1; if (wsrc < 0) wsrc += 14;
            val += x[l * 196 + ap * 14 + wsrc];
        }
        int bm = b - 1; if (bm < 0) bm += 14;
        int t1 = bm + kh - 1;
        if (t1 >= 0 && t1 < 14) {
            int wsrc = t1 - 1; if (wsrc < 0) wsrc += 14;
            val += x[(l + 128) * 196 + ap * 14 + wsrc];
        }
        g_U[e] = val;
    } else {
        int e = (blockIdx.x - U_BLOCKS) * 256 + threadIdx.x;  // < 294912, coalesced read
        int i = e / 1152;
        int k = e - i * 1152;
        g_Wt[(k >> 2) * 1024 + i * 4 + (k & 3)] = w[e];
    }
}

// Grid (a=14, i-tile=8), 256 threads = 8 warps. lane = output channel (i0+lane).
// Full K=1152 split across warps (144 k each). w via coalesced LDG from packed g_Wt.
__global__ __launch_bounds__(256, 1)
void gemm_kernel(float* __restrict__ y) {
    extern __shared__ float u_s[];       // [kq=9][b=14][l=128] = 16128 floats; reused as red

    const int a   = blockIdx.x;          // 0..13
    const int i0  = blockIdx.y * 32;
    const int tid = threadIdx.x;

    // ---- stage U rows ap = a-1 .. a+1 (zero outside [0,14)) ----
    float4* u4s = (float4*)u_s;
#pragma unroll
    for (int it = 0; it < 16; it++) {
        int idx = it * 256 + tid;                    // < 4096; valid < 4032
        if (idx < 4032) {
            int kj  = idx / 1344;                    // 5376/4
            int rem = idx - kj * 1344;
            int ap  = a - 1 + kj;
            float4 v = make_float4(0.f, 0.f, 0.f, 0.f);
            if (ap >= 0 && ap < 14) v = ((const float4*)g_U)[ap * 1344 + rem];
            u4s[idx] = v;
        }
    }
    __syncthreads();

    const int warp = tid >> 5;
    const int lane = tid & 31;

    float acc[14];
#pragma unroll
    for (int b = 0; b < 14; b++) acc[b] = 0.f;

    // w: lane reads float4 {k..k+3} for row i0+lane; consecutive lanes contiguous.
    const float4* wp = ((const float4*)g_Wt) + (warp * 36) * 256 + i0 + lane;
    const float4* u4 = (const float4*)u_s;
    const int k0 = warp * 144;

#pragma unroll 4
    for (int t = 0; t < 36; t++) {
        float4 wv = wp[t * 256];                     // coalesced LDG.128 (4 lines/warp)
        int k  = k0 + t * 4;
        int ub = (k >> 7) * 448 + ((k & 127) >> 2);  // float4 idx into u_s, b=0
#pragma unroll
        for (int b = 0; b < 14; b++) {
            float4 uv = u4[ub + b * 32];             // warp-broadcast LDS
            acc[b] = fmaf(wv.x, uv.x, acc[b]);
            acc[b] = fmaf(wv.y, uv.y, acc[b]);
            acc[b] = fmaf(wv.z, uv.z, acc[b]);
            acc[b] = fmaf(wv.w, uv.w, acc[b]);
        }
    }

    __syncthreads();                                 // u_s now reusable as red buffer
    float* red = u_s;                                // [warp][b][lane] = 3584 floats
#pragma unroll
    for (int b = 0; b < 14; b++) red[(warp * 14 + b) * 32 + lane] = acc[b];
    __syncthreads();

    for (int o = tid; o < 14 * 32; o += 256) {
        int b = o >> 5;
        int i = o & 31;
        float s = 0.f;
#pragma unroll
        for (int wq = 0; wq < 8; wq++) s += red[(wq * 14 + b) * 32 + i];
        y[(i0 + i) * 196 + a * 14 + b] = s;
    }
}

extern "C" void kernel_launch(void* const* d_in, const int* in_sizes, int n_in,
                              void* d_out, int out_size) {
    const float* x = (const float*)d_in[0];
    const float* w = (const float*)d_in[1];
    float* y = (float*)d_out;

    cudaFuncSetAttribute(gemm_kernel,
                         cudaFuncAttributeMaxDynamicSharedMemorySize, GEMM_SMEM);

    prep_kernel<<<U_BLOCKS + W_BLOCKS, 256>>>(x, w);
    gemm_kernel<<<dim3(14, 8), 256, GEMM_SMEM>>>(y);
}